// round 13
// baseline (speedup 1.0000x reference)
#include <cuda_runtime.h>
#include <math.h>
#include <stddef.h>

#define NN     4096
#define TT     16
#define FF     4
#define HIDC   64
#define NH     4
#define NCHUNK 512
#define CHSZ   8
#define CHLOG  3
#define NSUPER 32
#define SUPSZ  16
#define SUPLOG 4
#define PB     64        // persistent blocks (must stay 64: barrier uses >>6)
#define PT     1024      // threads per block

// ---------------------------------------------------------------------------
// Scratch
// ---------------------------------------------------------------------------
struct Scratch {
    float  Wh[NH * NN * HIDC];
    float  s1[NH * NN];
    float  s2[NH * NN];
    float  s2s[NH * NN];
    int    perm[NH * NN];
    float  A[NH * NN];
    float  B[NH * NN];
    float  csA[NH * NCHUNK * HIDC];   // within-super exclusive suffix (after P3)
    float  csB[NH * NCHUNK * HIDC];   // within-super exclusive prefix
    float  ssA[NH * NSUPER * HIDC];   // super totals -> exclusive suffix (after P4)
    float  ssB[NH * NSUPER * HIDC];
    double sufAsc[NH * (NN + 1)];
    double preBsc[NH * (NN + 1)];
    float  hcat[NN * NH * HIDC];
    // layer 2
    float  Wh2[NN * TT];
    float  s1o[NN], s2o[NN], s2so[NN];
    int    permo[NN];
    float  Ao[NN], Bo[NN];
    float  csA2[NCHUNK * TT], csB2[NCHUNK * TT];
    float  ssA2[NSUPER * TT], ssB2[NSUPER * TT];
    double sufA2sc[NN + 1], preB2sc[NN + 1];
};
__device__ Scratch S;

__device__ unsigned int g_bar[16];   // monotonic barrier counters (never reset)

// Grid barrier: epoch-target scheme. Counter only ever increments; each use
// waits for the next multiple of PB. Deterministic across graph replays.
__device__ __forceinline__ void gbar(int id)
{
    __syncthreads();
    if (threadIdx.x == 0) {
        __threadfence();
        const unsigned v = atomicAdd(&g_bar[id], 1u);
        const unsigned target = ((v >> 6) + 1u) << 6;     // PB = 64
        while (*(volatile unsigned int*)&g_bar[id] < target) __nanosleep(64);
    }
    __syncthreads();
}

// ---------------------------------------------------------------------------
// Sort + scalar-scan body (verbatim from the passing R11 kernel, pointerized).
// Whole 1024-thread block participates.
// ---------------------------------------------------------------------------
__device__ void sort_scan_body(const float* __restrict__ s2,
                               float* __restrict__ s2s,
                               int*   __restrict__ perm,
                               float* __restrict__ A,
                               float* __restrict__ B,
                               double* __restrict__ sufAsc,
                               double* __restrict__ preBsc,
                               float* key, int* sidx)
{
    const int t    = threadIdx.x;
    const int lane = t & 31;

    float k0[4]; int x0[4];
    #pragma unroll
    for (int m = 0; m < 4; m++) {
        const int i = t + m * 1024;
        k0[m] = s2[i];
        x0[m] = i;
    }

    #pragma unroll
    for (int k = 2; k <= 32; k <<= 1) {
        #pragma unroll
        for (int j = k >> 1; j >= 1; j >>= 1) {
            #pragma unroll
            for (int m = 0; m < 4; m++) {
                const int i = t + m * 1024;
                const bool up = ((i & k) == 0);
                const float ok = __shfl_xor_sync(0xffffffffu, k0[m], j);
                const int   oi = __shfl_xor_sync(0xffffffffu, x0[m], j);
                const bool lower = ((lane & j) == 0);
                const bool wantMin = (lower == up);
                const bool take = wantMin ? (ok < k0[m]) : (ok > k0[m]);
                if (take) { k0[m] = ok; x0[m] = oi; }
            }
        }
    }
    #pragma unroll
    for (int m = 0; m < 4; m++) {
        const int i = t + m * 1024;
        key[i] = k0[m]; sidx[i] = x0[m];
    }
    __syncthreads();

    for (int k = 64; k <= NN; k <<= 1) {
        for (int j = k >> 1; j >= 32; j >>= 1) {
            #pragma unroll
            for (int m = 0; m < 4; m++) {
                const int i = t + m * 1024;
                const int ixj = i ^ j;
                if (ixj > i) {
                    const bool up = ((i & k) == 0);
                    const float a = key[i], b = key[ixj];
                    if ((a > b) == up) {
                        key[i] = b; key[ixj] = a;
                        const int tmp = sidx[i]; sidx[i] = sidx[ixj]; sidx[ixj] = tmp;
                    }
                }
            }
            __syncthreads();
        }
        #pragma unroll
        for (int m = 0; m < 4; m++) {
            const int i = t + m * 1024;
            k0[m] = key[i]; x0[m] = sidx[i];
        }
        #pragma unroll
        for (int j = 16; j >= 1; j >>= 1) {
            #pragma unroll
            for (int m = 0; m < 4; m++) {
                const int i = t + m * 1024;
                const bool up = ((i & k) == 0);
                const float ok = __shfl_xor_sync(0xffffffffu, k0[m], j);
                const int   oi = __shfl_xor_sync(0xffffffffu, x0[m], j);
                const bool lower = ((lane & j) == 0);
                const bool wantMin = (lower == up);
                const bool take = wantMin ? (ok < k0[m]) : (ok > k0[m]);
                if (take) { k0[m] = ok; x0[m] = oi; }
            }
        }
        #pragma unroll
        for (int m = 0; m < 4; m++) {
            const int i = t + m * 1024;
            key[i] = k0[m]; sidx[i] = x0[m];
        }
        __syncthreads();
    }

    #pragma unroll
    for (int m = 0; m < 4; m++) {
        const int i = t + m * 1024;
        const float v = k0[m];
        s2s[i]  = v;
        perm[i] = x0[m];
        A[i]    = expf(v);
        B[i]    = expf(0.01f * v);
    }
    __syncthreads();

    // scalar fp64 scans
    double* seg = (double*)sidx;
    float av[4], bv[4];
    double la = 0.0, lb = 0.0;
    #pragma unroll
    for (int e = 0; e < 4; e++) {
        const float v = key[4 * t + e];
        av[e] = expf(v); bv[e] = expf(0.01f * v);
        la += (double)av[e]; lb += (double)bv[e];
    }
    seg[t] = la; seg[1024 + t] = lb;
    __syncthreads();

    for (int d = 1; d < 1024; d <<= 1) {
        double va = 0.0, vb = 0.0;
        if (t >= d) { va = seg[t - d]; vb = seg[1024 + t - d]; }
        __syncthreads();
        seg[t] += va; seg[1024 + t] += vb;
        __syncthreads();
    }

    const double exA = seg[t] - la;
    const double exB = seg[1024 + t] - lb;
    const double totA = seg[1023];
    const double totB = seg[2047];

    double runB = exB, runA = exA;
    #pragma unroll
    for (int e = 0; e < 4; e++) {
        const int p = 4 * t + e;
        preBsc[p] = runB;        runB += (double)bv[e];
        sufAsc[p] = totA - runA; runA += (double)av[e];
    }
    if (t == 1023) { preBsc[NN] = totB; sufAsc[NN] = 0.0; }
    __syncthreads();
}

// ---------------------------------------------------------------------------
// The persistent kernel
// ---------------------------------------------------------------------------
__global__ void __launch_bounds__(PT, 1)
k_persist(const float* __restrict__ x,
          const float* __restrict__ W,
          const float* __restrict__ a1,
          const float* __restrict__ a2,
          const float* __restrict__ Wo,
          const float* __restrict__ a1o,
          const float* __restrict__ a2o,
          float* __restrict__ out)
{
    __shared__ __align__(16) char sm[38656];
    const int t  = threadIdx.x;
    const int bx = blockIdx.x;
    const int gid = bx * PT + t;

    // ===== P0: s1/s2 via h @ (W @ a)  ====================================
    {
        float* wv = (float*)sm;                    // [NH][2][64]
        if (t < 512) {
            const int head = t >> 7, which = (t >> 6) & 1, r = t & 63;
            const float* Wp = W + head * 4096 + r * 64;
            const float* av = (which ? a2 : a1) + head * 64;
            float s = 0.f;
            #pragma unroll
            for (int o = 0; o < 64; o++) s = fmaf(Wp[o], av[o], s);
            wv[(head * 2 + which) * 64 + r] = s;
        }
        __syncthreads();
        if (gid < NH * NN) {
            const int head = gid >> 12, n = gid & 4095;
            const float4* x4 = (const float4*)x;
            const float* w1 = &wv[(head * 2 + 0) * 64];
            const float* w2 = &wv[(head * 2 + 1) * 64];
            float v1 = 0.f, v2 = 0.f;
            #pragma unroll
            for (int tt2 = 0; tt2 < 16; tt2++) {
                const float4 hv = x4[(size_t)tt2 * NN + n];
                v1 = fmaf(hv.x, w1[tt2*4+0], fmaf(hv.y, w1[tt2*4+1], fmaf(hv.z, w1[tt2*4+2], fmaf(hv.w, w1[tt2*4+3], v1))));
                v2 = fmaf(hv.x, w2[tt2*4+0], fmaf(hv.y, w2[tt2*4+1], fmaf(hv.z, w2[tt2*4+2], fmaf(hv.w, w2[tt2*4+3], v2))));
            }
            S.s1[head * NN + n] = v1;
            S.s2[head * NN + n] = v2;
        }
    }
    gbar(0);

    // ===== P1: blocks 0-3 sort heads; blocks 4-63 compute Wh GEMM ========
    if (bx < NH) {
        const int head = bx;
        sort_scan_body(S.s2 + head * NN, S.s2s + head * NN, S.perm + head * NN,
                       S.A + head * NN, S.B + head * NN,
                       S.sufAsc + head * (NN + 1), S.preBsc + head * (NN + 1),
                       (float*)sm, (int*)(sm + 16384));
    } else {
        float* sW = (float*)sm;                    // 64x65
        float* sh = (float*)(sm + 16640);          // 64x65
        for (int tile = bx - NH; tile < 256; tile += (PB - NH)) {
            const int head = tile >> 6;
            const int n0   = (tile & 63) << 6;
            for (int idx = t; idx < 4096; idx += PT)
                sW[(idx >> 6) * 65 + (idx & 63)] = W[head * 4096 + idx];
            {
                const int dn = t >> 4, rr = t & 15;
                const float4 v = ((const float4*)x)[(size_t)rr * NN + n0 + dn];
                sh[dn * 65 + rr * 4 + 0] = v.x;
                sh[dn * 65 + rr * 4 + 1] = v.y;
                sh[dn * 65 + rr * 4 + 2] = v.z;
                sh[dn * 65 + rr * 4 + 3] = v.w;
            }
            __syncthreads();
            const int tr = t >> 5, tc = t & 31;
            float a00 = 0.f, a01 = 0.f, a10 = 0.f, a11 = 0.f;
            #pragma unroll 8
            for (int k = 0; k < 64; k++) {
                const float av0 = sh[tr * 65 + k];
                const float av1 = sh[(tr + 32) * 65 + k];
                const float bv0 = sW[k * 65 + tc];
                const float bv1 = sW[k * 65 + tc + 32];
                a00 = fmaf(av0, bv0, a00); a01 = fmaf(av0, bv1, a01);
                a10 = fmaf(av1, bv0, a10); a11 = fmaf(av1, bv1, a11);
            }
            float* WhG = S.Wh + ((size_t)head * NN + n0) * HIDC;
            WhG[(size_t)tr * HIDC + tc]             = a00;
            WhG[(size_t)tr * HIDC + tc + 32]        = a01;
            WhG[(size_t)(tr + 32) * HIDC + tc]      = a10;
            WhG[(size_t)(tr + 32) * HIDC + tc + 32] = a11;
            __syncthreads();
        }
    }
    gbar(1);

    // ===== P2: chunk sums L0 =============================================
    for (int id = gid; id < NH * NCHUNK * HIDC; id += PB * PT) {
        const int c = id & 63, q = (id >> 6) & 511, head = id >> 15;
        const float* Wh = S.Wh + (size_t)head * NN * HIDC;
        const int*   pm = S.perm + head * NN;
        const float* Ap = S.A + head * NN;
        const float* Bp = S.B + head * NN;
        const int p0 = q * CHSZ;
        float sa = 0.f, sb = 0.f;
        #pragma unroll
        for (int e = 0; e < CHSZ; e++) {
            const int p = p0 + e;
            const float w = Wh[(size_t)pm[p] * HIDC + c];
            sa = fmaf(Ap[p], w, sa);
            sb = fmaf(Bp[p], w, sb);
        }
        S.csA[(size_t)head * NCHUNK * HIDC + q * HIDC + c] = sa;
        S.csB[(size_t)head * NCHUNK * HIDC + q * HIDC + c] = sb;
    }
    gbar(2);

    // ===== P3: within-super scans + super totals L0 ======================
    if (gid < NH * NSUPER * HIDC) {
        const int c = gid & 63, sq = (gid >> 6) & 31, head = gid >> 11;
        float* csA = S.csA + (size_t)head * NCHUNK * HIDC + c;
        float* csB = S.csB + (size_t)head * NCHUNK * HIDC + c;
        float va[SUPSZ], vb[SUPSZ];
        #pragma unroll
        for (int j = 0; j < SUPSZ; j++) {
            va[j] = csA[(sq * SUPSZ + j) * HIDC];
            vb[j] = csB[(sq * SUPSZ + j) * HIDC];
        }
        float run = 0.f;
        #pragma unroll
        for (int j = SUPSZ - 1; j >= 0; j--) { const float v = va[j]; csA[(sq * SUPSZ + j) * HIDC] = run; run += v; }
        S.ssA[(size_t)head * NSUPER * HIDC + sq * HIDC + c] = run;
        run = 0.f;
        #pragma unroll
        for (int j = 0; j < SUPSZ; j++) { const float v = vb[j]; csB[(sq * SUPSZ + j) * HIDC] = run; run += v; }
        S.ssB[(size_t)head * NSUPER * HIDC + sq * HIDC + c] = run;
    }
    gbar(3);

    // ===== P4: super-total scans L0 ======================================
    if (gid < NH * HIDC) {
        const int c = gid & 63, head = gid >> 6;
        float* ssA = S.ssA + (size_t)head * NSUPER * HIDC + c;
        float* ssB = S.ssB + (size_t)head * NSUPER * HIDC + c;
        float v[NSUPER];
        #pragma unroll
        for (int i = 0; i < NSUPER; i++) v[i] = ssA[i * HIDC];
        float run = 0.f;
        #pragma unroll
        for (int i = NSUPER - 1; i >= 0; i--) { const float tv = v[i]; ssA[i * HIDC] = run; run += tv; }
        #pragma unroll
        for (int i = 0; i < NSUPER; i++) v[i] = ssB[i * HIDC];
        run = 0.f;
        #pragma unroll
        for (int i = 0; i < NSUPER; i++) { const float tv = v[i]; ssB[i * HIDC] = run; run += tv; }
    }
    gbar(4);

    // ===== P5: combine L0 (warp per row) =================================
    {
        const int warpg = gid >> 5;
        const int lane  = t & 31;
        for (int row = warpg; row < NH * NN; row += (PB * PT) >> 5) {
            const int head = row >> 12, i = row & 4095;
            const float*  s1p  = S.s1  + head * NN;
            const float*  s2p  = S.s2  + head * NN;
            const float*  s2sp = S.s2s + head * NN;
            const int*    pm   = S.perm + head * NN;
            const float*  Ap   = S.A + head * NN;
            const float*  Bp   = S.B + head * NN;
            const float*  Wh   = S.Wh + (size_t)head * NN * HIDC;
            const float*  csA  = S.csA + (size_t)head * NCHUNK * HIDC;
            const float*  csB  = S.csB + (size_t)head * NCHUNK * HIDC;
            const float*  ssA  = S.ssA + (size_t)head * NSUPER * HIDC;
            const float*  ssB  = S.ssB + (size_t)head * NSUPER * HIDC;
            const double* sAs  = S.sufAsc + head * (NN + 1);
            const double* pBs  = S.preBsc + head * (NN + 1);

            const float s1v = s1p[i];
            const float ea  = expf(s1v);
            const float eb  = expf(0.01f * s1v);
            const float target = -s1v;
            int lo = 0, hi = NN;
            while (lo < hi) {
                const int mid = (lo + hi) >> 1;
                if (s2sp[mid] < target) lo = mid + 1; else hi = mid;
            }
            const int k = lo;
            const float tii = s1v + s2p[i];
            const float wii = expf(tii >= 0.f ? tii : 0.01f * tii);
            const double rd = 1.0 / ((double)ea * sAs[k] + (double)eb * pBs[k] - (double)wii);
            const int q  = (k >> CHLOG) < (NCHUNK - 1) ? (k >> CHLOG) : (NCHUNK - 1);
            const int sq = q >> SUPLOG;
            const int p0 = q << CHLOG;
            float coef[CHSZ]; int off[CHSZ];
            #pragma unroll
            for (int e = 0; e < CHSZ; e++) {
                const int p = p0 + e;
                coef[e] = (p >= k) ? ea * Ap[p] : eb * Bp[p];
                off[e]  = pm[p] * HIDC;
            }
            #pragma unroll
            for (int h2 = 0; h2 < 2; h2++) {
                const int c = lane + 32 * h2;
                float acc = ea * (csA[q * HIDC + c] + ssA[sq * HIDC + c])
                          + eb * (csB[q * HIDC + c] + ssB[sq * HIDC + c]);
                #pragma unroll
                for (int e = 0; e < CHSZ; e++)
                    acc = fmaf(coef[e], Wh[(size_t)off[e] + c], acc);
                const float num = acc - wii * Wh[(size_t)i * HIDC + c];
                float v = (float)((double)num * rd);
                v = (v > 0.f) ? v : expm1f(v);
                S.hcat[(size_t)i * (NH * HIDC) + head * HIDC + c] = v;
            }
        }
    }
    gbar(5);

    // ===== P6: gemm2 (64 rows per block) + s1o/s2o tail ==================
    {
        float* sW   = (float*)sm;                  // 256x17 = 17408B
        float* sh2  = (float*)(sm + 17408);        // 64x65  = 16640B
        float* sAcc = (float*)(sm + 17408 + 16640);// 64x17  = 4352B
        const int row0 = bx * 64;
        for (int idx = t; idx < 4096; idx += PT)
            sW[(idx >> 4) * 17 + (idx & 15)] = Wo[idx];
        const int tr = t >> 4, tc = t & 15;
        float acc = 0.f;
        for (int kc = 0; kc < 4; kc++) {
            __syncthreads();
            for (int idx = t; idx < 4096; idx += PT) {
                const int r = idx >> 6, k = idx & 63;
                sh2[r * 65 + k] = S.hcat[(size_t)(row0 + r) * 256 + kc * 64 + k];
            }
            __syncthreads();
            #pragma unroll 16
            for (int k = 0; k < 64; k++)
                acc = fmaf(sh2[tr * 65 + k], sW[(kc * 64 + k) * 17 + tc], acc);
        }
        S.Wh2[(row0 + tr) * TT + tc] = acc;
        sAcc[tr * 17 + tc] = acc;
        __syncthreads();
        if (t < 64) {
            const int r = t;
            float v1 = 0.f, v2 = 0.f;
            #pragma unroll
            for (int c = 0; c < 16; c++) {
                const float w = sAcc[r * 17 + c];
                v1 = fmaf(w, a1o[c], v1);
                v2 = fmaf(w, a2o[c], v2);
            }
            S.s1o[row0 + r] = v1;
            S.s2o[row0 + r] = v2;
        }
    }
    gbar(6);

    // ===== P7: block 0 does ALL of layer-2 sort + sums + scans ===========
    if (bx == 0) {
        sort_scan_body(S.s2o, S.s2so, S.permo, S.Ao, S.Bo,
                       S.sufA2sc, S.preB2sc,
                       (float*)sm, (int*)(sm + 16384));
        // chunk sums L1
        for (int id = t; id < NCHUNK * TT; id += PT) {
            const int c = id & 15, q = id >> 4;
            const int p0 = q * CHSZ;
            float sa = 0.f, sb = 0.f;
            #pragma unroll
            for (int e = 0; e < CHSZ; e++) {
                const int p = p0 + e;
                const float w = S.Wh2[(size_t)S.permo[p] * TT + c];
                sa = fmaf(S.Ao[p], w, sa);
                sb = fmaf(S.Bo[p], w, sb);
            }
            S.csA2[q * TT + c] = sa;
            S.csB2[q * TT + c] = sb;
        }
        __syncthreads();
        if (t < NSUPER * TT) {
            const int c = t & 15, sq = t >> 4;
            float va[SUPSZ], vb[SUPSZ];
            #pragma unroll
            for (int j = 0; j < SUPSZ; j++) {
                va[j] = S.csA2[(sq * SUPSZ + j) * TT + c];
                vb[j] = S.csB2[(sq * SUPSZ + j) * TT + c];
            }
            float run = 0.f;
            #pragma unroll
            for (int j = SUPSZ - 1; j >= 0; j--) { const float v = va[j]; S.csA2[(sq * SUPSZ + j) * TT + c] = run; run += v; }
            S.ssA2[sq * TT + c] = run;
            run = 0.f;
            #pragma unroll
            for (int j = 0; j < SUPSZ; j++) { const float v = vb[j]; S.csB2[(sq * SUPSZ + j) * TT + c] = run; run += v; }
            S.ssB2[sq * TT + c] = run;
        }
        __syncthreads();
        if (t < TT) {
            const int c = t;
            float v[NSUPER];
            #pragma unroll
            for (int i = 0; i < NSUPER; i++) v[i] = S.ssA2[i * TT + c];
            float run = 0.f;
            #pragma unroll
            for (int i = NSUPER - 1; i >= 0; i--) { const float tv = v[i]; S.ssA2[i * TT + c] = run; run += tv; }
            #pragma unroll
            for (int i = 0; i < NSUPER; i++) v[i] = S.ssB2[i * TT + c];
            run = 0.f;
            #pragma unroll
            for (int i = 0; i < NSUPER; i++) { const float tv = v[i]; S.ssB2[i * TT + c] = run; run += tv; }
        }
    }
    gbar(7);

    // ===== P8: combine L1 (half-warp per row) -> out =====================
    {
        const int warpg = gid >> 5;
        const int lane  = t & 31;
        const int half  = lane >> 4;
        const int c     = lane & 15;
        const int i     = warpg * 2 + half;
        if (i < NN) {
            const float s1v = S.s1o[i];
            const float ea  = expf(s1v);
            const float eb  = expf(0.01f * s1v);
            const float target = -s1v;
            int lo = 0, hi = NN;
            while (lo < hi) {
                const int mid = (lo + hi) >> 1;
                if (S.s2so[mid] < target) lo = mid + 1; else hi = mid;
            }
            const int k = lo;
            const float tii = s1v + S.s2o[i];
            const float wii = expf(tii >= 0.f ? tii : 0.01f * tii);
            const double rd = 1.0 / ((double)ea * S.sufA2sc[k] + (double)eb * S.preB2sc[k] - (double)wii);
            const int q  = (k >> CHLOG) < (NCHUNK - 1) ? (k >> CHLOG) : (NCHUNK - 1);
            const int sq = q >> SUPLOG;
            const int p0 = q << CHLOG;
            float acc = ea * (S.csA2[q * TT + c] + S.ssA2[sq * TT + c])
                      + eb * (S.csB2[q * TT + c] + S.ssB2[sq * TT + c]);
            #pragma unroll
            for (int e = 0; e < CHSZ; e++) {
                const int p = p0 + e;
                const float coef = (p >= k) ? ea * S.Ao[p] : eb * S.Bo[p];
                acc = fmaf(coef, S.Wh2[(size_t)S.permo[p] * TT + c], acc);
            }
            const float num = acc - wii * S.Wh2[(size_t)i * TT + c];
            out[(size_t)i * TT + c] = (float)((double)num * rd);
        }
    }
}

// ---------------------------------------------------------------------------
// launch — ONE kernel
// ---------------------------------------------------------------------------
extern "C" void kernel_launch(void* const* d_in, const int* in_sizes, int n_in,
                              void* d_out, int out_size)
{
    const float* x       = (const float*)d_in[0];
    const float* W_heads = (const float*)d_in[3];
    const float* a1h     = (const float*)d_in[4];
    const float* a2h     = (const float*)d_in[5];
    const float* W_out   = (const float*)d_in[6];
    const float* a1o     = (const float*)d_in[7];
    const float* a2o     = (const float*)d_in[8];
    float* out = (float*)d_out;

    k_persist<<<PB, PT>>>(x, W_heads, a1h, a2h, W_out, a1o, a2o, out);
}

// round 14
// speedup vs baseline: 1.1967x; 1.1967x over previous
#include <cuda_runtime.h>
#include <math.h>
#include <stddef.h>

#define NN     4096
#define TT     16
#define FF     4
#define HIDC   64
#define NH     4
#define NCHUNK 512
#define CHSZ   8
#define CHLOG  3
#define NSUPER 32
#define SUPSZ  16
#define SUPLOG 4

// ---------------------------------------------------------------------------
// Scratch
// ---------------------------------------------------------------------------
struct Scratch {
    float  Wh[NH * NN * HIDC];
    float  s1[NH * NN];
    float  s2[NH * NN];
    float  s2s[NH * NN];
    float  s2c[NH * 64];               // coarse table: s2s[64j]
    int    perm[NH * NN];
    float  A[NH * NN];
    float  B[NH * NN];
    float  csA[NH * NCHUNK * HIDC];    // within-super exclusive suffix
    float  csB[NH * NCHUNK * HIDC];    // within-super exclusive prefix
    float  ssA[NH * NSUPER * HIDC];    // super totals -> exclusive suffix
    float  ssB[NH * NSUPER * HIDC];
    double sufAsc[NH * (NN + 1)];
    double preBsc[NH * (NN + 1)];
    float  hcat[NN * NH * HIDC];
    // layer 2
    float  Wh2[NN * TT];
    float  s1o[NN], s2o[NN], s2so[NN];
    float  s2co[64];
    int    permo[NN];
    float  Ao[NN], Bo[NN];
    float  csA2[NCHUNK * TT], csB2[NCHUNK * TT];
    float  ssA2[NSUPER * TT], ssB2[NSUPER * TT];
    double sufA2sc[NN + 1], preB2sc[NN + 1];
};
__device__ Scratch S;

__device__ unsigned int g_ctr;   // monotonic epoch counter (never reset)

// ---------------------------------------------------------------------------
// Kernel 1: fused transpose(x) -> h, Wh = h @ W[head], s1/s2 dots
// grid (NN/64, NH), block 256   (verbatim from the 172us baseline)
// ---------------------------------------------------------------------------
__global__ void k_gemm1(const float* __restrict__ x,
                        const float* __restrict__ W,
                        const float* __restrict__ a1,
                        const float* __restrict__ a2)
{
    __shared__ float sW[64 * 65];
    __shared__ float sh[64 * 65];

    const int head = blockIdx.y;
    const int n0   = blockIdx.x * 64;
    const int t    = threadIdx.x;

    const float* Wp = W + head * 64 * 64;
    for (int idx = t; idx < 4096; idx += 256)
        sW[(idx >> 6) * 65 + (idx & 63)] = Wp[idx];

    {
        const int dn = t >> 2, f = t & 3;
        #pragma unroll
        for (int tt = 0; tt < TT; tt++)
            sh[dn * 65 + tt * 4 + f] = x[(size_t)tt * NN * FF + (size_t)(n0 + dn) * FF + f];
    }
    __syncthreads();

    const int tc = t & 15, tr = t >> 4;
    float acc[4][4];
    #pragma unroll
    for (int i = 0; i < 4; i++)
        #pragma unroll
        for (int j = 0; j < 4; j++) acc[i][j] = 0.f;

    for (int k = 0; k < 64; k++) {
        float av[4], bv[4];
        #pragma unroll
        for (int i = 0; i < 4; i++) av[i] = sh[(tr + 16 * i) * 65 + k];
        #pragma unroll
        for (int j = 0; j < 4; j++) bv[j] = sW[k * 65 + tc + 16 * j];
        #pragma unroll
        for (int i = 0; i < 4; i++)
            #pragma unroll
            for (int j = 0; j < 4; j++) acc[i][j] = fmaf(av[i], bv[j], acc[i][j]);
    }
    __syncthreads();

    float* __restrict__ WhG = S.Wh;
    #pragma unroll
    for (int i = 0; i < 4; i++) {
        const int r = tr + 16 * i;
        #pragma unroll
        for (int j = 0; j < 4; j++) {
            const int c = tc + 16 * j;
            sW[r * 65 + c] = acc[i][j];
            WhG[((size_t)head * NN + (n0 + r)) * HIDC + c] = acc[i][j];
        }
    }
    __syncthreads();

    if (t < 64) {
        const int r = t;
        const float* ap1 = a1 + head * HIDC;
        const float* ap2 = a2 + head * HIDC;
        float v1 = 0.f, v2 = 0.f;
        #pragma unroll
        for (int c = 0; c < 64; c++) {
            const float w = sW[r * 65 + c];
            v1 = fmaf(w, ap1[c], v1);
            v2 = fmaf(w, ap2[c], v2);
        }
        S.s1[head * NN + n0 + r] = v1;
        S.s2[head * NN + n0 + r] = v2;
    }
}

// ---------------------------------------------------------------------------
// Kernel 2: hcat @ W_out + s1o/s2o.  grid 256, block 256 (verbatim baseline)
// ---------------------------------------------------------------------------
__global__ void k_gemm2(const float* __restrict__ Wo,
                        const float* __restrict__ a1,
                        const float* __restrict__ a2)
{
    __shared__ float sW[256 * 17];
    __shared__ float sh2[16 * 257];
    __shared__ float sAcc[16 * 17];

    const float* __restrict__ hcat = S.hcat;
    const int row0 = blockIdx.x * 16;
    const int t    = threadIdx.x;

    for (int idx = t; idx < 4096; idx += 256)
        sW[(idx >> 4) * 17 + (idx & 15)] = Wo[idx];
    #pragma unroll
    for (int r = 0; r < 16; r++)
        sh2[r * 257 + t] = hcat[(size_t)(row0 + r) * 256 + t];
    __syncthreads();

    const int tc = t & 15, tr = t >> 4;
    float acc = 0.f;
    #pragma unroll 8
    for (int k = 0; k < 256; k++)
        acc = fmaf(sh2[tr * 257 + k], sW[k * 17 + tc], acc);

    S.Wh2[(row0 + tr) * TT + tc] = acc;
    sAcc[tr * 17 + tc] = acc;
    __syncthreads();

    if (t < 16) {
        const int r = t;
        float v1 = 0.f, v2 = 0.f;
        #pragma unroll
        for (int c = 0; c < 16; c++) {
            const float w = sAcc[r * 17 + c];
            v1 = fmaf(w, a1[c], v1);
            v2 = fmaf(w, a2[c], v2);
        }
        S.s1o[row0 + r] = v1;
        S.s2o[row0 + r] = v2;
    }
}

// ---------------------------------------------------------------------------
// Device body: bitonic sort + exp weights + coarse table + fp64 scalar scans.
// 1024-thread block. (Verified in R13 persistent run.)
// ---------------------------------------------------------------------------
__device__ void sort_scan_body(const float* __restrict__ s2,
                               float* __restrict__ s2s,
                               float* __restrict__ s2c,
                               int*   __restrict__ perm,
                               float* __restrict__ A,
                               float* __restrict__ B,
                               double* __restrict__ sufAsc,
                               double* __restrict__ preBsc,
                               float* key, int* sidx)
{
    const int t    = threadIdx.x;
    const int lane = t & 31;

    float k0[4]; int x0[4];
    #pragma unroll
    for (int m = 0; m < 4; m++) {
        const int i = t + m * 1024;
        k0[m] = s2[i];
        x0[m] = i;
    }

    #pragma unroll
    for (int k = 2; k <= 32; k <<= 1) {
        #pragma unroll
        for (int j = k >> 1; j >= 1; j >>= 1) {
            #pragma unroll
            for (int m = 0; m < 4; m++) {
                const int i = t + m * 1024;
                const bool up = ((i & k) == 0);
                const float ok = __shfl_xor_sync(0xffffffffu, k0[m], j);
                const int   oi = __shfl_xor_sync(0xffffffffu, x0[m], j);
                const bool lower = ((lane & j) == 0);
                const bool wantMin = (lower == up);
                const bool take = wantMin ? (ok < k0[m]) : (ok > k0[m]);
                if (take) { k0[m] = ok; x0[m] = oi; }
            }
        }
    }
    #pragma unroll
    for (int m = 0; m < 4; m++) {
        const int i = t + m * 1024;
        key[i] = k0[m]; sidx[i] = x0[m];
    }
    __syncthreads();

    for (int k = 64; k <= NN; k <<= 1) {
        for (int j = k >> 1; j >= 32; j >>= 1) {
            #pragma unroll
            for (int m = 0; m < 4; m++) {
                const int i = t + m * 1024;
                const int ixj = i ^ j;
                if (ixj > i) {
                    const bool up = ((i & k) == 0);
                    const float a = key[i], b = key[ixj];
                    if ((a > b) == up) {
                        key[i] = b; key[ixj] = a;
                        const int tmp = sidx[i]; sidx[i] = sidx[ixj]; sidx[ixj] = tmp;
                    }
                }
            }
            __syncthreads();
        }
        #pragma unroll
        for (int m = 0; m < 4; m++) {
            const int i = t + m * 1024;
            k0[m] = key[i]; x0[m] = sidx[i];
        }
        #pragma unroll
        for (int j = 16; j >= 1; j >>= 1) {
            #pragma unroll
            for (int m = 0; m < 4; m++) {
                const int i = t + m * 1024;
                const bool up = ((i & k) == 0);
                const float ok = __shfl_xor_sync(0xffffffffu, k0[m], j);
                const int   oi = __shfl_xor_sync(0xffffffffu, x0[m], j);
                const bool lower = ((lane & j) == 0);
                const bool wantMin = (lower == up);
                const bool take = wantMin ? (ok < k0[m]) : (ok > k0[m]);
                if (take) { k0[m] = ok; x0[m] = oi; }
            }
        }
        #pragma unroll
        for (int m = 0; m < 4; m++) {
            const int i = t + m * 1024;
            key[i] = k0[m]; sidx[i] = x0[m];
        }
        __syncthreads();
    }

    #pragma unroll
    for (int m = 0; m < 4; m++) {
        const int i = t + m * 1024;
        const float v = k0[m];
        s2s[i]  = v;
        perm[i] = x0[m];
        A[i]    = expf(v);
        B[i]    = expf(0.01f * v);
        if ((i & 63) == 0) s2c[i >> 6] = v;
    }
    __syncthreads();

    // scalar fp64 scans
    double* seg = (double*)sidx;
    float av[4], bv[4];
    double la = 0.0, lb = 0.0;
    #pragma unroll
    for (int e = 0; e < 4; e++) {
        const float v = key[4 * t + e];
        av[e] = expf(v); bv[e] = expf(0.01f * v);
        la += (double)av[e]; lb += (double)bv[e];
    }
    seg[t] = la; seg[1024 + t] = lb;
    __syncthreads();

    for (int d = 1; d < 1024; d <<= 1) {
        double va = 0.0, vb = 0.0;
        if (t >= d) { va = seg[t - d]; vb = seg[1024 + t - d]; }
        __syncthreads();
        seg[t] += va; seg[1024 + t] += vb;
        __syncthreads();
    }

    const double exA = seg[t] - la;
    const double exB = seg[1024 + t] - lb;
    const double totA = seg[1023];
    const double totB = seg[2047];

    double runB = exB, runA = exA;
    #pragma unroll
    for (int e = 0; e < 4; e++) {
        const int p = 4 * t + e;
        preBsc[p] = runB;        runB += (double)bv[e];
        sufAsc[p] = totA - runA; runA += (double)av[e];
    }
    if (t == 1023) { preBsc[NN] = totB; sufAsc[NN] = 0.0; }
    __syncthreads();
}

// ---------------------------------------------------------------------------
// Kernel 3: sortscan L0 wrapper — 1 block of 1024 per head
// ---------------------------------------------------------------------------
__global__ void __launch_bounds__(1024, 1) k_sortscan0()
{
    __shared__ float key[NN];
    __shared__ int   sidx[NN];
    const int head = blockIdx.x;
    sort_scan_body(S.s2 + head * NN, S.s2s + head * NN, S.s2c + head * 64,
                   S.perm + head * NN, S.A + head * NN, S.B + head * NN,
                   S.sufAsc + head * (NN + 1), S.preBsc + head * (NN + 1),
                   key, sidx);
}

// ---------------------------------------------------------------------------
// Kernel 4: chunk sums + within-super scans; LAST block does super-total scan.
// grid (NH, NSUPER) = 128 blocks, block 1024: thread = (chunk-in-super, chan).
// ---------------------------------------------------------------------------
__global__ void __launch_bounds__(1024, 1) k_chunksum0()
{
    __shared__ float sA[SUPSZ][HIDC + 1];
    __shared__ float sB[SUPSZ][HIDC + 1];
    __shared__ int   sLast;

    const int head = blockIdx.x;
    const int sq   = blockIdx.y;
    const float* __restrict__ Wh   = S.Wh   + (size_t)head * NN * HIDC;
    const int*   __restrict__ perm = S.perm + head * NN;
    const float* __restrict__ A    = S.A    + head * NN;
    const float* __restrict__ B    = S.B    + head * NN;
    float*       __restrict__ csA  = S.csA  + (size_t)head * NCHUNK * HIDC;
    float*       __restrict__ csB  = S.csB  + (size_t)head * NCHUNK * HIDC;

    const int t  = threadIdx.x;
    const int ql = t >> 6;          // 0..15
    const int c  = t & 63;

    {
        const int q  = sq * SUPSZ + ql;
        const int p0 = q * CHSZ;
        float sa = 0.f, sb = 0.f;
        #pragma unroll
        for (int e = 0; e < CHSZ; e++) {
            const int p = p0 + e;
            const float w = Wh[(size_t)perm[p] * HIDC + c];
            sa = fmaf(A[p], w, sa);
            sb = fmaf(B[p], w, sb);
        }
        sA[ql][c] = sa;
        sB[ql][c] = sb;
    }
    __syncthreads();

    if (t < HIDC) {
        const int cc = t;
        float run = 0.f;
        #pragma unroll
        for (int j = SUPSZ - 1; j >= 0; j--) {
            const float v = sA[j][cc];
            csA[(sq * SUPSZ + j) * HIDC + cc] = run;
            run += v;
        }
        S.ssA[(size_t)head * NSUPER * HIDC + sq * HIDC + cc] = run;
    } else if (t < 2 * HIDC) {
        const int cc = t - HIDC;
        float run = 0.f;
        #pragma unroll
        for (int j = 0; j < SUPSZ; j++) {
            const float v = sB[j][cc];
            csB[(sq * SUPSZ + j) * HIDC + cc] = run;
            run += v;
        }
        S.ssB[(size_t)head * NSUPER * HIDC + sq * HIDC + cc] = run;
    }

    // last-arriving block scans the super totals (all heads/channels)
    __threadfence();
    __syncthreads();
    if (t == 0) {
        const unsigned v = atomicAdd(&g_ctr, 1u);
        sLast = (((v + 1u) & 127u) == 0u) ? 1 : 0;   // 128 blocks per replay
    }
    __syncthreads();
    if (sLast) {
        __threadfence();
        if (t < NH * HIDC) {                 // A: exclusive suffix over supers
            const int h2 = t >> 6, cc = t & 63;
            float* base = S.ssA + (size_t)h2 * NSUPER * HIDC + cc;
            float v[NSUPER];
            #pragma unroll
            for (int i = 0; i < NSUPER; i++) v[i] = base[i * HIDC];
            float run = 0.f;
            #pragma unroll
            for (int i = NSUPER - 1; i >= 0; i--) { const float tv = v[i]; base[i * HIDC] = run; run += tv; }
        } else if (t < 2 * NH * HIDC) {      // B: exclusive prefix over supers
            const int u = t - NH * HIDC;
            const int h2 = u >> 6, cc = u & 63;
            float* base = S.ssB + (size_t)h2 * NSUPER * HIDC + cc;
            float v[NSUPER];
            #pragma unroll
            for (int i = 0; i < NSUPER; i++) v[i] = base[i * HIDC];
            float run = 0.f;
            #pragma unroll
            for (int i = 0; i < NSUPER; i++) { const float tv = v[i]; base[i * HIDC] = run; run += tv; }
        }
    }
}

// ---------------------------------------------------------------------------
// Kernel 5: per-row combine with two-level (coarse+fine) search.
// block 256 = IPB rows x C channels.
// ---------------------------------------------------------------------------
template<int C, bool DO_ELU, int L>
__global__ void k_combine(float* __restrict__ extOut, int rowStride)
{
    constexpr int IPB = 256 / C;
    __shared__ float  sEa[IPB], sEb[IPB], sWii[IPB];
    __shared__ double sRd[IPB];
    __shared__ float  sCoef[IPB][CHSZ];
    __shared__ int    sOff[IPB][CHSZ];
    __shared__ int    sQ[IPB];

    const int head = blockIdx.y;
    const float*  __restrict__ s1     = ((L == 0) ? S.s1     : S.s1o)  + head * NN;
    const float*  __restrict__ s2     = ((L == 0) ? S.s2     : S.s2o)  + head * NN;
    const float*  __restrict__ s2s    = ((L == 0) ? S.s2s    : S.s2so) + head * NN;
    const float*  __restrict__ s2c    = ((L == 0) ? S.s2c + head * 64 : S.s2co);
    const int*    __restrict__ perm   = ((L == 0) ? S.perm   : S.permo) + head * NN;
    const float*  __restrict__ A      = ((L == 0) ? S.A      : S.Ao)   + head * NN;
    const float*  __restrict__ B      = ((L == 0) ? S.B      : S.Bo)   + head * NN;
    const float*  __restrict__ Wh     = ((L == 0) ? S.Wh     : S.Wh2)  + (size_t)head * NN * C;
    const float*  __restrict__ csAs   = ((L == 0) ? S.csA    : S.csA2) + (size_t)head * NCHUNK * C;
    const float*  __restrict__ csBs   = ((L == 0) ? S.csB    : S.csB2) + (size_t)head * NCHUNK * C;
    const float*  __restrict__ ssAs   = ((L == 0) ? S.ssA    : S.ssA2) + (size_t)head * NSUPER * C;
    const float*  __restrict__ ssBs   = ((L == 0) ? S.ssB    : S.ssB2) + (size_t)head * NSUPER * C;
    const double* __restrict__ sufAsc = ((L == 0) ? S.sufAsc : S.sufA2sc) + head * (NN + 1);
    const double* __restrict__ preBsc = ((L == 0) ? S.preBsc : S.preB2sc) + head * (NN + 1);
    float* __restrict__ out = (L == 0) ? S.hcat : extOut;

    const int r = threadIdx.x / C;
    const int i = blockIdx.x * IPB + r;
    const int c = threadIdx.x % C;

    if (c == 0) {
        const float s1v = s1[i];
        const float ea  = expf(s1v);
        const float eb  = expf(0.01f * s1v);
        const float target = -s1v;
        // coarse: co = count of s2c[j] < target  (6 steps)
        int lo = 0, hi = 64;
        while (lo < hi) {
            const int mid = (lo + hi) >> 1;
            if (s2c[mid] < target) lo = mid + 1; else hi = mid;
        }
        const int co = lo;
        // fine window: k in [64(co-1)+1, 64co]  (<=6 steps)
        int l2, h2;
        if (co == 0) { l2 = 0; h2 = 0; }
        else { l2 = 64 * (co - 1) + 1; h2 = (co == 64) ? NN : 64 * co; }
        while (l2 < h2) {
            const int mid = (l2 + h2) >> 1;
            if (s2s[mid] < target) l2 = mid + 1; else h2 = mid;
        }
        const int k = l2;
        const int q = min(k >> CHLOG, NCHUNK - 1);
        const int p0 = q << CHLOG;
        #pragma unroll
        for (int e = 0; e < CHSZ; e++) {
            const int p = p0 + e;
            sCoef[r][e] = (p >= k) ? ea * A[p] : eb * B[p];
            sOff[r][e]  = perm[p] * C;
        }
        const float tii = s1v + s2[i];
        const float wii = expf(tii >= 0.f ? tii : 0.01f * tii);
        const double denom = (double)ea * sufAsc[k] + (double)eb * preBsc[k] - (double)wii;
        sEa[r] = ea;  sEb[r] = eb;  sWii[r] = wii;  sQ[r] = q;
        sRd[r] = 1.0 / denom;
    }
    __syncthreads();

    const float  ea  = sEa[r];
    const float  eb  = sEb[r];
    const float  wii = sWii[r];
    const double rd  = sRd[r];
    const int    q   = sQ[r];
    const int    sq  = q >> SUPLOG;

    float acc = ea * (csAs[q * C + c] + ssAs[sq * C + c])
              + eb * (csBs[q * C + c] + ssBs[sq * C + c]);

    #pragma unroll
    for (int e = 0; e < CHSZ; e++)
        acc = fmaf(sCoef[r][e], Wh[(size_t)sOff[r][e] + c], acc);

    const float num = acc - wii * Wh[(size_t)i * C + c];
    float v = (float)((double)num * rd);
    if (DO_ELU) v = (v > 0.f) ? v : expm1f(v);

    out[(size_t)i * rowStride + head * C + c] = v;
}

// ---------------------------------------------------------------------------
// Kernel 6: ALL of layer-2 prep in one single-block kernel:
// sort + scalar scans + chunk sums + within-super scans + super scans.
// ---------------------------------------------------------------------------
__global__ void __launch_bounds__(1024, 1) k_l2prep()
{
    __shared__ float key[NN];
    __shared__ int   sidx[NN];
    const int t = threadIdx.x;

    sort_scan_body(S.s2o, S.s2so, S.s2co, S.permo, S.Ao, S.Bo,
                   S.sufA2sc, S.preB2sc, key, sidx);

    // chunk sums (raw) -> csA2/csB2
    for (int id = t; id < NCHUNK * TT; id += 1024) {
        const int c = id & 15, q = id >> 4;
        const int p0 = q * CHSZ;
        float sa = 0.f, sb = 0.f;
        #pragma unroll
        for (int e = 0; e < CHSZ; e++) {
            const int p = p0 + e;
            const float w = S.Wh2[(size_t)S.permo[p] * TT + c];
            sa = fmaf(S.Ao[p], w, sa);
            sb = fmaf(S.Bo[p], w, sb);
        }
        S.csA2[q * TT + c] = sa;
        S.csB2[q * TT + c] = sb;
    }
    __syncthreads();

    // within-super scans + super totals (A: t<512, B: t>=512)
    if (t < 512) {
        const int sq = t >> 4, c = t & 15;
        float v[SUPSZ];
        #pragma unroll
        for (int j = 0; j < SUPSZ; j++) v[j] = S.csA2[(sq * SUPSZ + j) * TT + c];
        float run = 0.f;
        #pragma unroll
        for (int j = SUPSZ - 1; j >= 0; j--) { const float tv = v[j]; S.csA2[(sq * SUPSZ + j) * TT + c] = run; run += tv; }
        S.ssA2[sq * TT + c] = run;
    } else {
        const int u = t - 512;
        const int sq = u >> 4, c = u & 15;
        float v[SUPSZ];
        #pragma unroll
        for (int j = 0; j < SUPSZ; j++) v[j] = S.csB2[(sq * SUPSZ + j) * TT + c];
        float run = 0.f;
        #pragma unroll
        for (int j = 0; j < SUPSZ; j++) { const float tv = v[j]; S.csB2[(sq * SUPSZ + j) * TT + c] = run; run += tv; }
        S.ssB2[sq * TT + c] = run;
    }
    __syncthreads();

    // super-total scans
    if (t < TT) {
        const int c = t;
        float v[NSUPER];
        #pragma unroll
        for (int i = 0; i < NSUPER; i++) v[i] = S.ssA2[i * TT + c];
        float run = 0.f;
        #pragma unroll
        for (int i = NSUPER - 1; i >= 0; i--) { const float tv = v[i]; S.ssA2[i * TT + c] = run; run += tv; }
    } else if (t < 2 * TT) {
        const int c = t - TT;
        float v[NSUPER];
        #pragma unroll
        for (int i = 0; i < NSUPER; i++) v[i] = S.ssB2[i * TT + c];
        float run = 0.f;
        #pragma unroll
        for (int i = 0; i < NSUPER; i++) { const float tv = v[i]; S.ssB2[i * TT + c] = run; run += tv; }
    }
}

// ---------------------------------------------------------------------------
// launch — 7 kernels
// ---------------------------------------------------------------------------
extern "C" void kernel_launch(void* const* d_in, const int* in_sizes, int n_in,
                              void* d_out, int out_size)
{
    const float* x       = (const float*)d_in[0];
    const float* W_heads = (const float*)d_in[3];
    const float* a1h     = (const float*)d_in[4];
    const float* a2h     = (const float*)d_in[5];
    const float* W_out   = (const float*)d_in[6];
    const float* a1o     = (const float*)d_in[7];
    const float* a2o     = (const float*)d_in[8];
    float* out = (float*)d_out;

    // ---- layer 1 ----
    k_gemm1<<<dim3(NN / 64, NH), 256>>>(x, W_heads, a1h, a2h);
    k_sortscan0<<<NH, 1024>>>();
    k_chunksum0<<<dim3(NH, NSUPER), 1024>>>();
    k_combine<HIDC, true, 0><<<dim3(NN / 4, NH), 256>>>(nullptr, NH * HIDC);

    // ---- layer 2 ----
    k_gemm2<<<NN / 16, 256>>>(W_out, a1o, a2o);
    k_l2prep<<<1, 1024>>>();
    k_combine<TT, false, 1><<<dim3(NN / 16, 1), 256>>>(out, TT);
}

// round 16
// speedup vs baseline: 1.2601x; 1.0530x over previous
#include <cuda_runtime.h>
#include <math.h>
#include <stddef.h>

#define NN     4096
#define TT     16
#define FF     4
#define HIDC   64
#define NH     4
#define NCHUNK 512
#define CHSZ   8
#define CHLOG  3
#define NSUPER 32
#define SUPSZ  16
#define SUPLOG 4

// ---------------------------------------------------------------------------
// Scratch
// ---------------------------------------------------------------------------
struct __align__(16) Scratch {
    float  Wh[NH * NN * HIDC];
    float  s1[NH * NN];
    float  s2[NH * NN];
    float  s2s[NH * NN];
    float  s2c[NH * 64];               // coarse table: s2s[64j]
    int    perm[NH * NN];
    float  A[NH * NN];
    float  B[NH * NN];
    float  csA[NH * NCHUNK * HIDC];    // within-super exclusive suffix
    float  csB[NH * NCHUNK * HIDC];    // within-super exclusive prefix
    float  ssA[NH * NSUPER * HIDC];    // super totals -> exclusive suffix
    float  ssB[NH * NSUPER * HIDC];
    double sufAsc[NH * (NN + 1)];
    double preBsc[NH * (NN + 1)];
    float  hcat[NN * NH * HIDC];
    // layer 2
    float  Wh2[NN * TT];
    float  s1o[NN], s2o[NN], s2so[NN];
    float  s2co[64];
    int    permo[NN];
    float  Ao[NN], Bo[NN];
    float  csA2[NCHUNK * TT], csB2[NCHUNK * TT];
    float  ssA2[NSUPER * TT], ssB2[NSUPER * TT];
    double sufA2sc[NN + 1], preB2sc[NN + 1];
};
__device__ Scratch S;

__device__ unsigned int g_ctr;   // monotonic epoch counter (never reset)

// ---------------------------------------------------------------------------
// Kernel 1: fused transpose(x) -> h, Wh = h @ W[head], s1/s2 dots
// grid (NN/64, NH), block 256
// ---------------------------------------------------------------------------
__global__ void k_gemm1(const float* __restrict__ x,
                        const float* __restrict__ W,
                        const float* __restrict__ a1,
                        const float* __restrict__ a2)
{
    __shared__ float sW[64 * 65];
    __shared__ float sh[64 * 65];

    const int head = blockIdx.y;
    const int n0   = blockIdx.x * 64;
    const int t    = threadIdx.x;

    const float* Wp = W + head * 64 * 64;
    for (int idx = t; idx < 4096; idx += 256)
        sW[(idx >> 6) * 65 + (idx & 63)] = Wp[idx];

    {
        const int dn = t >> 2, f = t & 3;
        #pragma unroll
        for (int tt = 0; tt < TT; tt++)
            sh[dn * 65 + tt * 4 + f] = x[(size_t)tt * NN * FF + (size_t)(n0 + dn) * FF + f];
    }
    __syncthreads();

    const int tc = t & 15, tr = t >> 4;
    float acc[4][4];
    #pragma unroll
    for (int i = 0; i < 4; i++)
        #pragma unroll
        for (int j = 0; j < 4; j++) acc[i][j] = 0.f;

    for (int k = 0; k < 64; k++) {
        float av[4], bv[4];
        #pragma unroll
        for (int i = 0; i < 4; i++) av[i] = sh[(tr + 16 * i) * 65 + k];
        #pragma unroll
        for (int j = 0; j < 4; j++) bv[j] = sW[k * 65 + tc + 16 * j];
        #pragma unroll
        for (int i = 0; i < 4; i++)
            #pragma unroll
            for (int j = 0; j < 4; j++) acc[i][j] = fmaf(av[i], bv[j], acc[i][j]);
    }
    __syncthreads();

    float* __restrict__ WhG = S.Wh;
    #pragma unroll
    for (int i = 0; i < 4; i++) {
        const int r = tr + 16 * i;
        #pragma unroll
        for (int j = 0; j < 4; j++) {
            const int c = tc + 16 * j;
            sW[r * 65 + c] = acc[i][j];
            WhG[((size_t)head * NN + (n0 + r)) * HIDC + c] = acc[i][j];
        }
    }
    __syncthreads();

    if (t < 64) {
        const int r = t;
        const float* ap1 = a1 + head * HIDC;
        const float* ap2 = a2 + head * HIDC;
        float v1 = 0.f, v2 = 0.f;
        #pragma unroll
        for (int c = 0; c < 64; c++) {
            const float w = sW[r * 65 + c];
            v1 = fmaf(w, ap1[c], v1);
            v2 = fmaf(w, ap2[c], v2);
        }
        S.s1[head * NN + n0 + r] = v1;
        S.s2[head * NN + n0 + r] = v2;
    }
}

// ---------------------------------------------------------------------------
// Kernel 2: hcat @ W_out + s1o/s2o.  grid 256, block 256
// ---------------------------------------------------------------------------
__global__ void k_gemm2(const float* __restrict__ Wo,
                        const float* __restrict__ a1,
                        const float* __restrict__ a2)
{
    __shared__ float sW[256 * 17];
    __shared__ float sh2[16 * 257];
    __shared__ float sAcc[16 * 17];

    const float* __restrict__ hcat = S.hcat;
    const int row0 = blockIdx.x * 16;
    const int t    = threadIdx.x;

    for (int idx = t; idx < 4096; idx += 256)
        sW[(idx >> 4) * 17 + (idx & 15)] = Wo[idx];
    #pragma unroll
    for (int r = 0; r < 16; r++)
        sh2[r * 257 + t] = hcat[(size_t)(row0 + r) * 256 + t];
    __syncthreads();

    const int tc = t & 15, tr = t >> 4;
    float acc = 0.f;
    #pragma unroll 8
    for (int k = 0; k < 256; k++)
        acc = fmaf(sh2[tr * 257 + k], sW[k * 17 + tc], acc);

    S.Wh2[(row0 + tr) * TT + tc] = acc;
    sAcc[tr * 17 + tc] = acc;
    __syncthreads();

    if (t < 16) {
        const int r = t;
        float v1 = 0.f, v2 = 0.f;
        #pragma unroll
        for (int c = 0; c < 16; c++) {
            const float w = sAcc[r * 17 + c];
            v1 = fmaf(w, a1[c], v1);
            v2 = fmaf(w, a2[c], v2);
        }
        S.s1o[row0 + r] = v1;
        S.s2o[row0 + r] = v2;
    }
}

// ---------------------------------------------------------------------------
// Device body: bitonic sort + exp weights + coarse table + fp64 scalar scans.
// ---------------------------------------------------------------------------
__device__ void sort_scan_body(const float* __restrict__ s2,
                               float* __restrict__ s2s,
                               float* __restrict__ s2c,
                               int*   __restrict__ perm,
                               float* __restrict__ A,
                               float* __restrict__ B,
                               double* __restrict__ sufAsc,
                               double* __restrict__ preBsc,
                               float* key, int* sidx)
{
    const int t    = threadIdx.x;
    const int lane = t & 31;

    float k0[4]; int x0[4];
    #pragma unroll
    for (int m = 0; m < 4; m++) {
        const int i = t + m * 1024;
        k0[m] = s2[i];
        x0[m] = i;
    }

    #pragma unroll
    for (int k = 2; k <= 32; k <<= 1) {
        #pragma unroll
        for (int j = k >> 1; j >= 1; j >>= 1) {
            #pragma unroll
            for (int m = 0; m < 4; m++) {
                const int i = t + m * 1024;
                const bool up = ((i & k) == 0);
                const float ok = __shfl_xor_sync(0xffffffffu, k0[m], j);
                const int   oi = __shfl_xor_sync(0xffffffffu, x0[m], j);
                const bool lower = ((lane & j) == 0);
                const bool wantMin = (lower == up);
                const bool take = wantMin ? (ok < k0[m]) : (ok > k0[m]);
                if (take) { k0[m] = ok; x0[m] = oi; }
            }
        }
    }
    #pragma unroll
    for (int m = 0; m < 4; m++) {
        const int i = t + m * 1024;
        key[i] = k0[m]; sidx[i] = x0[m];
    }
    __syncthreads();

    for (int k = 64; k <= NN; k <<= 1) {
        for (int j = k >> 1; j >= 32; j >>= 1) {
            #pragma unroll
            for (int m = 0; m < 4; m++) {
                const int i = t + m * 1024;
                const int ixj = i ^ j;
                if (ixj > i) {
                    const bool up = ((i & k) == 0);
                    const float a = key[i], b = key[ixj];
                    if ((a > b) == up) {
                        key[i] = b; key[ixj] = a;
                        const int tmp = sidx[i]; sidx[i] = sidx[ixj]; sidx[ixj] = tmp;
                    }
                }
            }
            __syncthreads();
        }
        #pragma unroll
        for (int m = 0; m < 4; m++) {
            const int i = t + m * 1024;
            k0[m] = key[i]; x0[m] = sidx[i];
        }
        #pragma unroll
        for (int j = 16; j >= 1; j >>= 1) {
            #pragma unroll
            for (int m = 0; m < 4; m++) {
                const int i = t + m * 1024;
                const bool up = ((i & k) == 0);
                const float ok = __shfl_xor_sync(0xffffffffu, k0[m], j);
                const int   oi = __shfl_xor_sync(0xffffffffu, x0[m], j);
                const bool lower = ((lane & j) == 0);
                const bool wantMin = (lower == up);
                const bool take = wantMin ? (ok < k0[m]) : (ok > k0[m]);
                if (take) { k0[m] = ok; x0[m] = oi; }
            }
        }
        #pragma unroll
        for (int m = 0; m < 4; m++) {
            const int i = t + m * 1024;
            key[i] = k0[m]; sidx[i] = x0[m];
        }
        __syncthreads();
    }

    #pragma unroll
    for (int m = 0; m < 4; m++) {
        const int i = t + m * 1024;
        const float v = k0[m];
        s2s[i]  = v;
        perm[i] = x0[m];
        A[i]    = expf(v);
        B[i]    = expf(0.01f * v);
        if ((i & 63) == 0) s2c[i >> 6] = v;
    }
    __syncthreads();

    // scalar fp64 scans
    double* seg = (double*)sidx;
    float av[4], bv[4];
    double la = 0.0, lb = 0.0;
    #pragma unroll
    for (int e = 0; e < 4; e++) {
        const float v = key[4 * t + e];
        av[e] = expf(v); bv[e] = expf(0.01f * v);
        la += (double)av[e]; lb += (double)bv[e];
    }
    seg[t] = la; seg[1024 + t] = lb;
    __syncthreads();

    for (int d = 1; d < 1024; d <<= 1) {
        double va = 0.0, vb = 0.0;
        if (t >= d) { va = seg[t - d]; vb = seg[1024 + t - d]; }
        __syncthreads();
        seg[t] += va; seg[1024 + t] += vb;
        __syncthreads();
    }

    const double exA = seg[t] - la;
    const double exB = seg[1024 + t] - lb;
    const double totA = seg[1023];
    const double totB = seg[2047];

    double runB = exB, runA = exA;
    #pragma unroll
    for (int e = 0; e < 4; e++) {
        const int p = 4 * t + e;
        preBsc[p] = runB;        runB += (double)bv[e];
        sufAsc[p] = totA - runA; runA += (double)av[e];
    }
    if (t == 1023) { preBsc[NN] = totB; sufAsc[NN] = 0.0; }
    __syncthreads();
}

// ---------------------------------------------------------------------------
// Kernel 3: sortscan L0 wrapper — 1 block of 1024 per head
// ---------------------------------------------------------------------------
__global__ void __launch_bounds__(1024, 1) k_sortscan0()
{
    __shared__ float key[NN];
    __shared__ int   sidx[NN];
    const int head = blockIdx.x;
    sort_scan_body(S.s2 + head * NN, S.s2s + head * NN, S.s2c + head * 64,
                   S.perm + head * NN, S.A + head * NN, S.B + head * NN,
                   S.sufAsc + head * (NN + 1), S.preBsc + head * (NN + 1),
                   key, sidx);
}

// ---------------------------------------------------------------------------
// Kernel 4: chunk sums + within-super scans; LAST block does super-total scan.
// grid (NH, NSUPER) = 128 blocks, block 1024.
// ---------------------------------------------------------------------------
__global__ void __launch_bounds__(1024, 1) k_chunksum0()
{
    __shared__ float sA[SUPSZ][HIDC + 1];
    __shared__ float sB[SUPSZ][HIDC + 1];
    __shared__ int   sLast;

    const int head = blockIdx.x;
    const int sq   = blockIdx.y;
    const float* __restrict__ Wh   = S.Wh   + (size_t)head * NN * HIDC;
    const int*   __restrict__ perm = S.perm + head * NN;
    const float* __restrict__ A    = S.A    + head * NN;
    const float* __restrict__ B    = S.B    + head * NN;
    float*       __restrict__ csA  = S.csA  + (size_t)head * NCHUNK * HIDC;
    float*       __restrict__ csB  = S.csB  + (size_t)head * NCHUNK * HIDC;

    const int t  = threadIdx.x;
    const int ql = t >> 6;          // 0..15
    const int c  = t & 63;

    {
        const int q  = sq * SUPSZ + ql;
        const int p0 = q * CHSZ;
        float sa = 0.f, sb = 0.f;
        #pragma unroll
        for (int e = 0; e < CHSZ; e++) {
            const int p = p0 + e;
            const float w = Wh[(size_t)perm[p] * HIDC + c];
            sa = fmaf(A[p], w, sa);
            sb = fmaf(B[p], w, sb);
        }
        sA[ql][c] = sa;
        sB[ql][c] = sb;
    }
    __syncthreads();

    if (t < HIDC) {
        const int cc = t;
        float run = 0.f;
        #pragma unroll
        for (int j = SUPSZ - 1; j >= 0; j--) {
            const float v = sA[j][cc];
            csA[(sq * SUPSZ + j) * HIDC + cc] = run;
            run += v;
        }
        S.ssA[(size_t)head * NSUPER * HIDC + sq * HIDC + cc] = run;
    } else if (t < 2 * HIDC) {
        const int cc = t - HIDC;
        float run = 0.f;
        #pragma unroll
        for (int j = 0; j < SUPSZ; j++) {
            const float v = sB[j][cc];
            csB[(sq * SUPSZ + j) * HIDC + cc] = run;
            run += v;
        }
        S.ssB[(size_t)head * NSUPER * HIDC + sq * HIDC + cc] = run;
    }

    __threadfence();
    __syncthreads();
    if (t == 0) {
        const unsigned v = atomicAdd(&g_ctr, 1u);
        sLast = (((v + 1u) & 127u) == 0u) ? 1 : 0;
    }
    __syncthreads();
    if (sLast) {
        __threadfence();
        if (t < NH * HIDC) {
            const int h2 = t >> 6, cc = t & 63;
            float* base = S.ssA + (size_t)h2 * NSUPER * HIDC + cc;
            float v[NSUPER];
            #pragma unroll
            for (int i = 0; i < NSUPER; i++) v[i] = base[i * HIDC];
            float run = 0.f;
            #pragma unroll
            for (int i = NSUPER - 1; i >= 0; i--) { const float tv = v[i]; base[i * HIDC] = run; run += tv; }
        } else if (t < 2 * NH * HIDC) {
            const int u = t - NH * HIDC;
            const int h2 = u >> 6, cc = u & 63;
            float* base = S.ssB + (size_t)h2 * NSUPER * HIDC + cc;
            float v[NSUPER];
            #pragma unroll
            for (int i = 0; i < NSUPER; i++) v[i] = base[i * HIDC];
            float run = 0.f;
            #pragma unroll
            for (int i = 0; i < NSUPER; i++) { const float tv = v[i]; base[i * HIDC] = run; run += tv; }
        }
    }
}

// ---------------------------------------------------------------------------
// Kernel 5: per-row combine, float4-vectorized workers (4 channels/thread).
// block 256 = IPB rows x (C/4) lanes.
// ---------------------------------------------------------------------------
template<int C, bool DO_ELU, int L>
__global__ void k_combine(float* __restrict__ extOut, int rowStride)
{
    constexpr int LPR = C / 4;          // lanes per row
    constexpr int IPB = 256 / LPR;      // rows per block
    __shared__ float  sEa[IPB], sEb[IPB], sWii[IPB];
    __shared__ double sRd[IPB];
    __shared__ float  sCoef[IPB][CHSZ];
    __shared__ int    sOff[IPB][CHSZ];
    __shared__ int    sQ[IPB];

    const int head = blockIdx.y;
    const float*  __restrict__ s1     = ((L == 0) ? S.s1     : S.s1o)  + head * NN;
    const float*  __restrict__ s2     = ((L == 0) ? S.s2     : S.s2o)  + head * NN;
    const float*  __restrict__ s2s    = ((L == 0) ? S.s2s    : S.s2so) + head * NN;
    const float*  __restrict__ s2c    = ((L == 0) ? S.s2c + head * 64 : S.s2co);
    const int*    __restrict__ perm   = ((L == 0) ? S.perm   : S.permo) + head * NN;
    const float*  __restrict__ A      = ((L == 0) ? S.A      : S.Ao)   + head * NN;
    const float*  __restrict__ B      = ((L == 0) ? S.B      : S.Bo)   + head * NN;
    const float*  __restrict__ Wh     = ((L == 0) ? S.Wh     : S.Wh2)  + (size_t)head * NN * C;
    const float*  __restrict__ csAs   = ((L == 0) ? S.csA    : S.csA2) + (size_t)head * NCHUNK * C;
    const float*  __restrict__ csBs   = ((L == 0) ? S.csB    : S.csB2) + (size_t)head * NCHUNK * C;
    const float*  __restrict__ ssAs   = ((L == 0) ? S.ssA    : S.ssA2) + (size_t)head * NSUPER * C;
    const float*  __restrict__ ssBs   = ((L == 0) ? S.ssB    : S.ssB2) + (size_t)head * NSUPER * C;
    const double* __restrict__ sufAsc = ((L == 0) ? S.sufAsc : S.sufA2sc) + head * (NN + 1);
    const double* __restrict__ preBsc = ((L == 0) ? S.preBsc : S.preB2sc) + head * (NN + 1);
    float* __restrict__ out = (L == 0) ? S.hcat : extOut;

    const int r    = threadIdx.x / LPR;
    const int lane = threadIdx.x % LPR;
    const int i    = blockIdx.x * IPB + r;
    const int c4   = lane * 4;

    if (lane == 0) {
        const float s1v = s1[i];
        const float ea  = expf(s1v);
        const float eb  = expf(0.01f * s1v);
        const float target = -s1v;
        int lo = 0, hi = 64;
        while (lo < hi) {
            const int mid = (lo + hi) >> 1;
            if (s2c[mid] < target) lo = mid + 1; else hi = mid;
        }
        const int co = lo;
        int l2, h2;
        if (co == 0) { l2 = 0; h2 = 0; }
        else { l2 = 64 * (co - 1) + 1; h2 = (co == 64) ? NN : 64 * co; }
        while (l2 < h2) {
            const int mid = (l2 + h2) >> 1;
            if (s2s[mid] < target) l2 = mid + 1; else h2 = mid;
        }
        const int k = l2;
        const int q = min(k >> CHLOG, NCHUNK - 1);
        const int p0 = q << CHLOG;
        #pragma unroll
        for (int e = 0; e < CHSZ; e++) {
            const int p = p0 + e;
            sCoef[r][e] = (p >= k) ? ea * A[p] : eb * B[p];
            sOff[r][e]  = perm[p] * C;
        }
        const float tii = s1v + s2[i];
        const float wii = expf(tii >= 0.f ? tii : 0.01f * tii);
        const double denom = (double)ea * sufAsc[k] + (double)eb * preBsc[k] - (double)wii;
        sEa[r] = ea;  sEb[r] = eb;  sWii[r] = wii;  sQ[r] = q;
        sRd[r] = 1.0 / denom;
    }
    __syncthreads();

    const float  ea  = sEa[r];
    const float  eb  = sEb[r];
    const float  wii = sWii[r];
    const double rd  = sRd[r];
    const int    q   = sQ[r];
    const int    sq  = q >> SUPLOG;

    const float4 cA = *(const float4*)(csAs + q * C + c4);
    const float4 sAv= *(const float4*)(ssAs + sq * C + c4);
    const float4 cB = *(const float4*)(csBs + q * C + c4);
    const float4 sBv= *(const float4*)(ssBs + sq * C + c4);

    float a0 = ea * (cA.x + sAv.x) + eb * (cB.x + sBv.x);
    float a1_ = ea * (cA.y + sAv.y) + eb * (cB.y + sBv.y);
    float a2_ = ea * (cA.z + sAv.z) + eb * (cB.z + sBv.z);
    float a3 = ea * (cA.w + sAv.w) + eb * (cB.w + sBv.w);

    #pragma unroll
    for (int e = 0; e < CHSZ; e++) {
        const float cf = sCoef[r][e];
        const float4 w4 = *(const float4*)(Wh + (size_t)sOff[r][e] + c4);
        a0 = fmaf(cf, w4.x, a0);
        a1_ = fmaf(cf, w4.y, a1_);
        a2_ = fmaf(cf, w4.z, a2_);
        a3 = fmaf(cf, w4.w, a3);
    }

    const float4 wd = *(const float4*)(Wh + (size_t)i * C + c4);
    float v0 = (float)((double)(a0 - wii * wd.x) * rd);
    float v1 = (float)((double)(a1_ - wii * wd.y) * rd);
    float v2 = (float)((double)(a2_ - wii * wd.z) * rd);
    float v3 = (float)((double)(a3 - wii * wd.w) * rd);
    if (DO_ELU) {
        v0 = (v0 > 0.f) ? v0 : expm1f(v0);
        v1 = (v1 > 0.f) ? v1 : expm1f(v1);
        v2 = (v2 > 0.f) ? v2 : expm1f(v2);
        v3 = (v3 > 0.f) ? v3 : expm1f(v3);
    }
    *(float4*)(out + (size_t)i * rowStride + head * C + c4) = make_float4(v0, v1, v2, v3);
}

// ---------------------------------------------------------------------------
// Kernel 6: ALL of layer-2 prep in one single-block kernel.
// ---------------------------------------------------------------------------
__global__ void __launch_bounds__(1024, 1) k_l2prep()
{
    __shared__ float key[NN];
    __shared__ int   sidx[NN];
    const int t = threadIdx.x;

    sort_scan_body(S.s2o, S.s2so, S.s2co, S.permo, S.Ao, S.Bo,
                   S.sufA2sc, S.preB2sc, key, sidx);

    for (int id = t; id < NCHUNK * TT; id += 1024) {
        const int c = id & 15, q = id >> 4;
        const int p0 = q * CHSZ;
        float sa = 0.f, sb = 0.f;
        #pragma unroll
        for (int e = 0; e < CHSZ; e++) {
            const int p = p0 + e;
            const float w = S.Wh2[(size_t)S.permo[p] * TT + c];
            sa = fmaf(S.Ao[p], w, sa);
            sb = fmaf(S.Bo[p], w, sb);
        }
        S.csA2[q * TT + c] = sa;
        S.csB2[q * TT + c] = sb;
    }
    __syncthreads();

    if (t < 512) {
        const int sq = t >> 4, c = t & 15;
        float v[SUPSZ];
        #pragma unroll
        for (int j = 0; j < SUPSZ; j++) v[j] = S.csA2[(sq * SUPSZ + j) * TT + c];
        float run = 0.f;
        #pragma unroll
        for (int j = SUPSZ - 1; j >= 0; j--) { const float tv = v[j]; S.csA2[(sq * SUPSZ + j) * TT + c] = run; run += tv; }
        S.ssA2[sq * TT + c] = run;
    } else {
        const int u = t - 512;
        const int sq = u >> 4, c = u & 15;
        float v[SUPSZ];
        #pragma unroll
        for (int j = 0; j < SUPSZ; j++) v[j] = S.csB2[(sq * SUPSZ + j) * TT + c];
        float run = 0.f;
        #pragma unroll
        for (int j = 0; j < SUPSZ; j++) { const float tv = v[j]; S.csB2[(sq * SUPSZ + j) * TT + c] = run; run += tv; }
        S.ssB2[sq * TT + c] = run;
    }
    __syncthreads();

    if (t < TT) {
        const int c = t;
        float v[NSUPER];
        #pragma unroll
        for (int i = 0; i < NSUPER; i++) v[i] = S.ssA2[i * TT + c];
        float run = 0.f;
        #pragma unroll
        for (int i = NSUPER - 1; i >= 0; i--) { const float tv = v[i]; S.ssA2[i * TT + c] = run; run += tv; }
    } else if (t < 2 * TT) {
        const int c = t - TT;
        float v[NSUPER];
        #pragma unroll
        for (int i = 0; i < NSUPER; i++) v[i] = S.ssB2[i * TT + c];
        float run = 0.f;
        #pragma unroll
        for (int i = 0; i < NSUPER; i++) { const float tv = v[i]; S.ssB2[i * TT + c] = run; run += tv; }
    }
}

// ---------------------------------------------------------------------------
// launch — 7 kernels
// ---------------------------------------------------------------------------
extern "C" void kernel_launch(void* const* d_in, const int* in_sizes, int n_in,
                              void* d_out, int out_size)
{
    const float* x       = (const float*)d_in[0];
    const float* W_heads = (const float*)d_in[3];
    const float* a1h     = (const float*)d_in[4];
    const float* a2h     = (const float*)d_in[5];
    const float* W_out   = (const float*)d_in[6];
    const float* a1o     = (const float*)d_in[7];
    const float* a2o     = (const float*)d_in[8];
    float* out = (float*)d_out;

    // ---- layer 1 ----
    k_gemm1<<<dim3(NN / 64, NH), 256>>>(x, W_heads, a1h, a2h);
    k_sortscan0<<<NH, 1024>>>();
    k_chunksum0<<<dim3(NH, NSUPER), 1024>>>();
    k_combine<HIDC, true, 0><<<dim3(NN / 16, NH), 256>>>(nullptr, NH * HIDC);

    // ---- layer 2 ----
    k_gemm2<<<NN / 16, 256>>>(W_out, a1o, a2o);
    k_l2prep<<<1, 1024>>>();
    k_combine<TT, false, 1><<<dim3(NN / 64, 1), 256>>>(out, TT);
}